// round 9
// baseline (speedup 1.0000x reference)
#include <cuda_runtime.h>
#include <cuda_fp16.h>
#include <cstdint>

#define BB 8
#define SS 2048
#define DD 128
#define NTH 512
#define NCH 32                    // chunks of 64 keys
#define OUT_W_OFF ((size_t)BB * SS * DD)

#define RSB 272                   // Q/K/V smem row stride (136 halfs)
#define QLO_D 34816
#define KLO_D 17408
#define VLO_D 17408
#define PRS 144                   // P smem row stride (64 keys*2B + 16 pad)
#define PLO_D 18432

#define QH_OFF 0                  // Q hi 34816 + lo 34816
#define KH_OFF 69632              // K hi 17408 + lo 17408 (single buf)
#define VH_OFF 104448             // 2 bufs x (hi 17408 + lo 17408)
#define VBUFB 34816
#define PH_OFF 174080             // P hi 18432 + lo 18432
#define CM_OFF 210944             // cm[128][2]
#define LS_OFF 211968             // l[128][2]
#define WV_OFF 212992             // winv[128]
#define SMEM_TOTAL 213504

__device__ __half gQh[(size_t)BB * SS * DD];
__device__ __half gQl[(size_t)BB * SS * DD];
__device__ __half gKh[(size_t)BB * SS * DD];
__device__ __half gKl[(size_t)BB * SS * DD];
__device__ __half gVh[(size_t)BB * SS * DD];
__device__ __half gVl[(size_t)BB * SS * DD];

// ============================= helpers =====================================
__device__ __forceinline__ uint32_t smem_u32(const void* p) {
    uint32_t a;
    asm("{ .reg .u64 t; cvta.to.shared.u64 t, %1; cvt.u32.u64 %0, t; }" : "=r"(a) : "l"(p));
    return a;
}
__device__ __forceinline__ void cpa16(uint32_t dst, const void* src) {
    asm volatile("cp.async.cg.shared.global [%0], [%1], 16;" :: "r"(dst), "l"(src));
}
#define CPA_COMMIT() asm volatile("cp.async.commit_group;")
#define CPA_WAIT1()  asm volatile("cp.async.wait_group 1;")
#define CPA_WAIT0()  asm volatile("cp.async.wait_group 0;")
#define PBAR(id)     asm volatile("bar.sync %0, 64;" :: "r"(id) : "memory")

__device__ __forceinline__ void ldsm4(uint32_t& r0, uint32_t& r1, uint32_t& r2, uint32_t& r3,
                                      uint32_t a) {
    asm volatile("ldmatrix.sync.aligned.m8n8.x4.shared.b16 {%0,%1,%2,%3}, [%4];"
                 : "=r"(r0), "=r"(r1), "=r"(r2), "=r"(r3) : "r"(a));
}
__device__ __forceinline__ void ldsm4t(uint32_t& r0, uint32_t& r1, uint32_t& r2, uint32_t& r3,
                                       uint32_t a) {
    asm volatile("ldmatrix.sync.aligned.m8n8.x4.trans.shared.b16 {%0,%1,%2,%3}, [%4];"
                 : "=r"(r0), "=r"(r1), "=r"(r2), "=r"(r3) : "r"(a));
}
__device__ __forceinline__ void mma16816(float* c, uint32_t a0, uint32_t a1, uint32_t a2,
                                         uint32_t a3, uint32_t b0, uint32_t b1) {
    asm volatile("mma.sync.aligned.m16n8k16.row.col.f32.f16.f16.f32 "
                 "{%0,%1,%2,%3}, {%4,%5,%6,%7}, {%8,%9}, {%0,%1,%2,%3};"
                 : "+f"(c[0]), "+f"(c[1]), "+f"(c[2]), "+f"(c[3])
                 : "r"(a0), "r"(a1), "r"(a2), "r"(a3), "r"(b0), "r"(b1));
}
__device__ __forceinline__ void split2(float a, float b, uint32_t& hi, uint32_t& lo) {
    __half ha = __float2half_rn(a), hb = __float2half_rn(b);
    __half la = __float2half_rn(a - __half2float(ha));
    __half lb = __float2half_rn(b - __half2float(hb));
    hi = (uint32_t)__half_as_ushort(ha) | ((uint32_t)__half_as_ushort(hb) << 16);
    lo = (uint32_t)__half_as_ushort(la) | ((uint32_t)__half_as_ushort(lb) << 16);
}
__device__ __forceinline__ void sts32(uint32_t a, uint32_t v) {
    asm volatile("st.shared.b32 [%0], %1;" :: "r"(a), "r"(v) : "memory");
}

// =========================== prep: fp32 -> hi/lo ===========================
__global__ void prep_split(const float* __restrict__ Q, const float* __restrict__ K,
                           const float* __restrict__ V) {
    size_t i = (size_t)blockIdx.x * 256 + threadIdx.x;
    const float* s;
    __half *dh, *dl;
    if (blockIdx.y == 0)      { s = Q; dh = gQh; dl = gQl; }
    else if (blockIdx.y == 1) { s = K; dh = gKh; dl = gKl; }
    else                      { s = V; dh = gVh; dl = gVl; }
    float x = s[i];
    __half h = __float2half_rn(x);
    dh[i] = h;
    dl[i] = __float2half_rn(x - __half2float(h));
}

// stage one 64-row hi/lo chunk, full CTA (512 threads)
__device__ __forceinline__ void stage64(uint32_t dH, const __half* sH, const __half* sL) {
    int t = threadIdx.x;
    #pragma unroll
    for (int i = 0; i < 2; i++) {
        int idx = t + NTH * i;                // 0..1023
        int r = idx >> 4, c = idx & 15;
        uint32_t off = (uint32_t)(r * RSB + c * 16);
        cpa16(dH + off, sH + (size_t)r * DD + c * 8);
        cpa16(dH + KLO_D + off, sL + (size_t)r * DD + c * 8);
    }
}

// ============================= main kernel =================================
__global__ __launch_bounds__(NTH, 1)
void attn_mma(float* __restrict__ out) {
    extern __shared__ __align__(1024) unsigned char sm[];
    const uint32_t sb = smem_u32(sm);
    const int t = threadIdx.x, lane = t & 31, w = t >> 5;
    const int pair = w >> 1, kw = w & 1;       // key-half for S, dv-half for O
    const int b = blockIdx.x >> 4, q0 = (blockIdx.x & 15) * 128;

    const size_t rowbase = (size_t)b * SS;
    const __half* qh = gQh + (rowbase + q0) * DD;
    const __half* ql = gQl + (rowbase + q0) * DD;
    const __half* kh = gKh + rowbase * DD;
    const __half* kl = gKl + rowbase * DD;
    const __half* vh = gVh + rowbase * DD;
    const __half* vl = gVl + rowbase * DD;

    const uint32_t qa0 = sb + QH_OFF +
        (uint32_t)((pair * 16 + (lane & 15)) * RSB + (lane >> 4) * 16);
    const uint32_t krowoff =
        (uint32_t)(((lane & 7) + ((lane >> 4) & 1) * 8) * RSB + ((lane >> 3) & 1) * 16);
    const uint32_t vrowoff =
        (uint32_t)(((lane & 7) + ((lane >> 3) & 1) * 8) * RSB + ((lane >> 4) & 1) * 16);
    const uint32_t kbase = sb + KH_OFF + (uint32_t)(kw * 32 * RSB);
    const uint32_t pa0 = sb + PH_OFF +
        (uint32_t)((pair * 16 + (lane & 15)) * PRS + (lane >> 4) * 16);
    const int r0q = pair * 16 + (lane >> 2);   // thread rows: r0q, r0q+8
    const uint32_t ps0 = sb + PH_OFF +
        (uint32_t)(r0q * PRS + kw * 64 + (lane & 3) * 4);

    // ---- prologue: Q + K0 + V0 ----
    {
        int tt = t;
        #pragma unroll
        for (int i = 0; i < 4; i++) {
            int idx = tt + NTH * i;            // 0..2047
            int r = idx >> 4, c = idx & 15;
            uint32_t off = (uint32_t)(r * RSB + c * 16);
            cpa16(sb + QH_OFF + off, qh + (size_t)r * DD + c * 8);
            cpa16(sb + QH_OFF + QLO_D + off, ql + (size_t)r * DD + c * 8);
        }
    }
    stage64(sb + KH_OFF, kh, kl);
    stage64(sb + VH_OFF, vh, vl);
    CPA_COMMIT();

    float O[8][4];
    #pragma unroll
    for (int n = 0; n < 8; n++) { O[n][0] = 0.f; O[n][1] = 0.f; O[n][2] = 0.f; O[n][3] = 0.f; }
    float m0 = -3.402823466e38f, m1 = -3.402823466e38f;
    float l0 = 0.f, l1 = 0.f;

    float* cmsm = (float*)(sm + CM_OFF);
    float* wrow0 = out + OUT_W_OFF + (rowbase + q0 + r0q) * SS + kw * 32 + 2 * (lane & 3);
    float* wrow1 = wrow0 + (size_t)8 * SS;

    // =========================== chunk loop ================================
    #pragma unroll 1
    for (int j = 0; j < NCH; j++) {
        if (j + 1 < NCH) {                     // V(j+1): full-chunk overlap
            stage64(sb + VH_OFF + (uint32_t)((j + 1) & 1) * VBUFB,
                    vh + (size_t)(j + 1) * 64 * DD, vl + (size_t)(j + 1) * 64 * DD);
            CPA_COMMIT();
            CPA_WAIT1();                       // K(j), V(j) done; V(j+1) may pend
        } else {
            CPA_WAIT0();
        }
        __syncthreads();                       // B1: staged data visible

        // ---- S(j): 16 rows x 32 keys (this warp's key-half), 3-term ----
        float S[4][4];
        #pragma unroll
        for (int r = 0; r < 4; r++) { S[r][0] = 0.f; S[r][1] = 0.f; S[r][2] = 0.f; S[r][3] = 0.f; }
        #pragma unroll
        for (int kt = 0; kt < 8; kt++) {
            uint32_t qa = qa0 + kt * 32;
            uint32_t qh0, qh1, qh2, qh3, ql0, ql1, ql2, ql3;
            ldsm4(qh0, qh1, qh2, qh3, qa);
            ldsm4(ql0, ql1, ql2, ql3, qa + QLO_D);
            #pragma unroll
            for (int ng = 0; ng < 2; ng++) {
                uint32_t ka = kbase + (uint32_t)(ng * 16 * RSB) + krowoff + kt * 32;
                uint32_t kh0, kh1, kh2, kh3, kl0, kl1, kl2, kl3;
                ldsm4(kh0, kh1, kh2, kh3, ka);
                ldsm4(kl0, kl1, kl2, kl3, ka + KLO_D);
                mma16816(S[2 * ng], qh0, qh1, qh2, qh3, kh0, kh1);
                mma16816(S[2 * ng], ql0, ql1, ql2, ql3, kh0, kh1);
                mma16816(S[2 * ng], qh0, qh1, qh2, qh3, kl0, kl1);
                mma16816(S[2 * ng + 1], qh0, qh1, qh2, qh3, kh2, kh3);
                mma16816(S[2 * ng + 1], ql0, ql1, ql2, ql3, kh2, kh3);
                mma16816(S[2 * ng + 1], qh0, qh1, qh2, qh3, kl2, kl3);
            }
        }

        // warp-local chunk max -> smem for pair exchange
        float cm0 = fmaxf(fmaxf(S[0][0], S[0][1]), fmaxf(S[1][0], S[1][1]));
        float cm1 = fmaxf(fmaxf(S[0][2], S[0][3]), fmaxf(S[1][2], S[1][3]));
        cm0 = fmaxf(cm0, fmaxf(fmaxf(S[2][0], S[2][1]), fmaxf(S[3][0], S[3][1])));
        cm1 = fmaxf(cm1, fmaxf(fmaxf(S[2][2], S[2][3]), fmaxf(S[3][2], S[3][3])));
        cm0 = fmaxf(cm0, __shfl_xor_sync(0xffffffffu, cm0, 1));
        cm0 = fmaxf(cm0, __shfl_xor_sync(0xffffffffu, cm0, 2));
        cm1 = fmaxf(cm1, __shfl_xor_sync(0xffffffffu, cm1, 1));
        cm1 = fmaxf(cm1, __shfl_xor_sync(0xffffffffu, cm1, 2));
        if ((lane & 3) == 0) {
            cmsm[r0q * 2 + kw] = cm0;
            cmsm[(r0q + 8) * 2 + kw] = cm1;
        }
        __syncthreads();                       // B2: K consumed + cm visible
        if (j + 1 < NCH) {                     // K(j+1) under scalar + PV
            stage64(sb + KH_OFF, kh + (size_t)(j + 1) * 64 * DD,
                    kl + (size_t)(j + 1) * 64 * DD);
            CPA_COMMIT();
        }

        // raw scores to gmem (fixup normalizes later)
        #pragma unroll
        for (int nt = 0; nt < 4; nt++) {
            *(float2*)(wrow0 + j * 64 + nt * 8) = make_float2(S[nt][0], S[nt][1]);
            *(float2*)(wrow1 + j * 64 + nt * 8) = make_float2(S[nt][2], S[nt][3]);
        }

        // shared online softmax update
        float nm0 = fmaxf(m0, fmaxf(cmsm[r0q * 2], cmsm[r0q * 2 + 1]));
        float nm1 = fmaxf(m1, fmaxf(cmsm[(r0q + 8) * 2], cmsm[(r0q + 8) * 2 + 1]));
        float a0 = __expf(m0 - nm0), a1 = __expf(m1 - nm1);
        m0 = nm0; m1 = nm1;
        l0 *= a0; l1 *= a1;
        #pragma unroll
        for (int nt = 0; nt < 4; nt++) {
            S[nt][0] = __expf(S[nt][0] - nm0);
            S[nt][1] = __expf(S[nt][1] - nm0);
            S[nt][2] = __expf(S[nt][2] - nm1);
            S[nt][3] = __expf(S[nt][3] - nm1);
            l0 += S[nt][0] + S[nt][1];
            l1 += S[nt][2] + S[nt][3];
        }
        #pragma unroll
        for (int n = 0; n < 8; n++) {
            O[n][0] *= a0; O[n][1] *= a0;
            O[n][2] *= a1; O[n][3] *= a1;
        }

        // P (fp16 hi/lo) to smem exchange buffer
        #pragma unroll
        for (int nt = 0; nt < 4; nt++) {
            uint32_t h0, lo0, h1, lo1;
            split2(S[nt][0], S[nt][1], h0, lo0);
            split2(S[nt][2], S[nt][3], h1, lo1);
            sts32(ps0 + nt * 16, h0);
            sts32(ps0 + nt * 16 + PLO_D, lo0);
            sts32(ps0 + 8 * PRS + nt * 16, h1);
            sts32(ps0 + 8 * PRS + nt * 16 + PLO_D, lo1);
        }
        PBAR(1 + pair);                        // B3: pair sees full 64-key P

        // ---- PV(j): all 64 keys x this warp's 64 dv columns, 3-term ----
        const uint32_t vbH = sb + VH_OFF + (uint32_t)(j & 1) * VBUFB;
        #pragma unroll
        for (int kt = 0; kt < 4; kt++) {
            uint32_t ph0, ph1, ph2, ph3, pl0, pl1, pl2, pl3;
            ldsm4(ph0, ph1, ph2, ph3, pa0 + kt * 32);
            ldsm4(pl0, pl1, pl2, pl3, pa0 + kt * 32 + PLO_D);
            #pragma unroll
            for (int ng = 0; ng < 4; ng++) {
                uint32_t va = vbH + (uint32_t)(kt * 16 * RSB) + vrowoff +
                              (uint32_t)((kw * 64 + ng * 16) * 2);
                uint32_t x0, x1, x2, x3, y0, y1, y2, y3;
                ldsm4t(x0, x1, x2, x3, va);
                ldsm4t(y0, y1, y2, y3, va + VLO_D);
                mma16816(O[2 * ng], ph0, ph1, ph2, ph3, x0, x1);
                mma16816(O[2 * ng], pl0, pl1, pl2, pl3, x0, x1);
                mma16816(O[2 * ng], ph0, ph1, ph2, ph3, y0, y1);
                mma16816(O[2 * ng + 1], ph0, ph1, ph2, ph3, x2, x3);
                mma16816(O[2 * ng + 1], pl0, pl1, pl2, pl3, x2, x3);
                mma16816(O[2 * ng + 1], ph0, ph1, ph2, ph3, y2, y3);
            }
        }
        __syncthreads();                       // B4: V(j), P consumed
    }

    // =========================== epilogue ==================================
    l0 += __shfl_xor_sync(0xffffffffu, l0, 1);
    l0 += __shfl_xor_sync(0xffffffffu, l0, 2);
    l1 += __shfl_xor_sync(0xffffffffu, l1, 1);
    l1 += __shfl_xor_sync(0xffffffffu, l1, 2);
    float* lsm = (float*)(sm + LS_OFF);
    float* wvs = (float*)(sm + WV_OFF);
    if ((lane & 3) == 0) {
        lsm[r0q * 2 + kw] = l0;
        lsm[(r0q + 8) * 2 + kw] = l1;
    }
    __syncthreads();
    const float lt0 = lsm[r0q * 2] + lsm[r0q * 2 + 1];
    const float lt1 = lsm[(r0q + 8) * 2] + lsm[(r0q + 8) * 2 + 1];
    const float linv0 = 1.0f / lt0, linv1 = 1.0f / lt1;
    if (kw == 0 && (lane & 3) == 0) {
        wvs[r0q] = __expf(-m0) * linv0;
        wvs[r0q + 8] = __expf(-m1) * linv1;
    }

    float* orow0 = out + (rowbase + q0 + r0q) * DD + kw * 64 + 2 * (lane & 3);
    float* orow1 = orow0 + (size_t)8 * DD;
    #pragma unroll
    for (int ng = 0; ng < 4; ng++) {
        *(float2*)(orow0 + ng * 16)     = make_float2(O[2 * ng][0] * linv0, O[2 * ng][1] * linv0);
        *(float2*)(orow0 + ng * 16 + 8) = make_float2(O[2 * ng + 1][0] * linv0, O[2 * ng + 1][1] * linv0);
        *(float2*)(orow1 + ng * 16)     = make_float2(O[2 * ng][2] * linv1, O[2 * ng][3] * linv1);
        *(float2*)(orow1 + ng * 16 + 8) = make_float2(O[2 * ng + 1][2] * linv1, O[2 * ng + 1][3] * linv1);
    }
    __syncthreads();

    // ======================= W fixup sweep (this CTA) ======================
    float4* wbase = (float4*)(out + OUT_W_OFF + (rowbase + q0) * SS);
    #pragma unroll 4
    for (int i = 0; i < 128; i++) {
        int fi = t + NTH * i;                  // 0..65535
        float wv = wvs[fi >> 9];
        float4 v = wbase[fi];
        v.x = __expf(v.x) * wv;
        v.y = __expf(v.y) * wv;
        v.z = __expf(v.z) * wv;
        v.w = __expf(v.w) * wv;
        wbase[fi] = v;
    }
}

// ===========================================================================
extern "C" void kernel_launch(void* const* d_in, const int* in_sizes, int n_in,
                              void* d_out, int out_size) {
    const float* Q = (const float*)d_in[0];
    const float* K = (const float*)d_in[1];
    const float* V = (const float*)d_in[2];
    float* out = (float*)d_out;

    cudaFuncSetAttribute(attn_mma, cudaFuncAttributeMaxDynamicSharedMemorySize, SMEM_TOTAL);

    prep_split<<<dim3((BB * SS * DD) / 256, 3), 256>>>(Q, K, V);
    attn_mma<<<BB * (SS / 128), NTH, SMEM_TOTAL>>>(out);
}

// round 10
// speedup vs baseline: 1.0610x; 1.0610x over previous
#include <cuda_runtime.h>
#include <cuda_fp16.h>
#include <cstdint>

#define BB 8
#define SS 2048
#define DD 128
#define NTH 512
#define NCHG 16                   // 64-key chunks per group (group owns 1024 keys)
#define OUT_W_OFF ((size_t)BB * SS * DD)

#define RSB 272                   // smem row stride bytes (136 halfs)
#define QLO_D 34816
#define KLO_D 17408

#define QH_OFF 0                  // Q hi 34816 + lo 34816
#define GK_OFF 69632              // per group: K hi 17408, K lo 17408, V0 17408, V1 17408
#define GRP_B  69632
#define OMRG   69632              // O merge buffer (group0 region, post-loop)
#define MT_OFF 208896             // Mtilde[2][128]
#define LS_OFF 209920             // l[2][128]
#define WV_OFF 210944             // winv[128]
#define SMEM_TOTAL 211456

__device__ __half gQh[(size_t)BB * SS * DD];
__device__ __half gQl[(size_t)BB * SS * DD];
__device__ __half gKh[(size_t)BB * SS * DD];
__device__ __half gKl[(size_t)BB * SS * DD];
__device__ __half gVh[(size_t)BB * SS * DD];
__device__ __half gVl[(size_t)BB * SS * DD];

// ============================= helpers =====================================
__device__ __forceinline__ uint32_t smem_u32(const void* p) {
    uint32_t a;
    asm("{ .reg .u64 t; cvta.to.shared.u64 t, %1; cvt.u32.u64 %0, t; }" : "=r"(a) : "l"(p));
    return a;
}
__device__ __forceinline__ void cpa16(uint32_t dst, const void* src) {
    asm volatile("cp.async.cg.shared.global [%0], [%1], 16;" :: "r"(dst), "l"(src));
}
#define CPA_COMMIT() asm volatile("cp.async.commit_group;")
#define CPA_WAIT1()  asm volatile("cp.async.wait_group 1;")
#define CPA_WAIT0()  asm volatile("cp.async.wait_group 0;")
#define GBAR(id)     asm volatile("bar.sync %0, 256;" :: "r"(id) : "memory")

__device__ __forceinline__ void ldsm4(uint32_t& r0, uint32_t& r1, uint32_t& r2, uint32_t& r3,
                                      uint32_t a) {
    asm volatile("ldmatrix.sync.aligned.m8n8.x4.shared.b16 {%0,%1,%2,%3}, [%4];"
                 : "=r"(r0), "=r"(r1), "=r"(r2), "=r"(r3) : "r"(a));
}
__device__ __forceinline__ void ldsm4t(uint32_t& r0, uint32_t& r1, uint32_t& r2, uint32_t& r3,
                                       uint32_t a) {
    asm volatile("ldmatrix.sync.aligned.m8n8.x4.trans.shared.b16 {%0,%1,%2,%3}, [%4];"
                 : "=r"(r0), "=r"(r1), "=r"(r2), "=r"(r3) : "r"(a));
}
__device__ __forceinline__ void mma16816(float* c, uint32_t a0, uint32_t a1, uint32_t a2,
                                         uint32_t a3, uint32_t b0, uint32_t b1) {
    asm volatile("mma.sync.aligned.m16n8k16.row.col.f32.f16.f16.f32 "
                 "{%0,%1,%2,%3}, {%4,%5,%6,%7}, {%8,%9}, {%0,%1,%2,%3};"
                 : "+f"(c[0]), "+f"(c[1]), "+f"(c[2]), "+f"(c[3])
                 : "r"(a0), "r"(a1), "r"(a2), "r"(a3), "r"(b0), "r"(b1));
}
__device__ __forceinline__ void split2(float a, float b, uint32_t& hi, uint32_t& lo) {
    __half ha = __float2half_rn(a), hb = __float2half_rn(b);
    __half la = __float2half_rn(a - __half2float(ha));
    __half lb = __float2half_rn(b - __half2float(hb));
    hi = (uint32_t)__half_as_ushort(ha) | ((uint32_t)__half_as_ushort(hb) << 16);
    lo = (uint32_t)__half_as_ushort(la) | ((uint32_t)__half_as_ushort(lb) << 16);
}

// =========================== prep: fp32 -> hi/lo ===========================
__global__ void prep_split(const float* __restrict__ Q, const float* __restrict__ K,
                           const float* __restrict__ V) {
    size_t i = (size_t)blockIdx.x * 256 + threadIdx.x;
    const float* s;
    __half *dh, *dl;
    if (blockIdx.y == 0)      { s = Q; dh = gQh; dl = gQl; }
    else if (blockIdx.y == 1) { s = K; dh = gKh; dl = gKl; }
    else                      { s = V; dh = gVh; dl = gVl; }
    float x = s[i];
    __half h = __float2half_rn(x);
    dh[i] = h;
    dl[i] = __float2half_rn(x - __half2float(h));
}

// stage 64-row hi+lo chunk (group's 256 threads)
__device__ __forceinline__ void stage64g(int tg, uint32_t dH,
                                         const __half* sH, const __half* sL) {
    #pragma unroll
    for (int i = 0; i < 4; i++) {
        int idx = tg + 256 * i;               // 0..1023
        int r = idx >> 4, c = idx & 15;
        uint32_t off = (uint32_t)(r * RSB + c * 16);
        cpa16(dH + off, sH + (size_t)r * DD + c * 8);
        cpa16(dH + KLO_D + off, sL + (size_t)r * DD + c * 8);
    }
}
// stage 64-row hi-only chunk
__device__ __forceinline__ void stage64h(int tg, uint32_t dH, const __half* sH) {
    #pragma unroll
    for (int i = 0; i < 4; i++) {
        int idx = tg + 256 * i;
        int r = idx >> 4, c = idx & 15;
        cpa16(dH + (uint32_t)(r * RSB + c * 16), sH + (size_t)r * DD + c * 8);
    }
}

// ============================= main kernel =================================
__global__ __launch_bounds__(NTH, 1)
void attn_mma(float* __restrict__ out) {
    extern __shared__ __align__(1024) unsigned char sm[];
    const uint32_t sb = smem_u32(sm);
    const int t = threadIdx.x, lane = t & 31, w = t >> 5;
    const int g = t >> 8, tg = t & 255, gw = w & 7;
    const int b = blockIdx.x >> 4, q0 = (blockIdx.x & 15) * 128;

    const size_t rowbase = (size_t)b * SS;
    const size_t keyoff = (size_t)g * 1024 * DD;
    const __half* qh = gQh + (rowbase + q0) * DD;
    const __half* ql = gQl + (rowbase + q0) * DD;
    const __half* kh = gKh + rowbase * DD + keyoff;
    const __half* kl = gKl + rowbase * DD + keyoff;
    const __half* vh = gVh + rowbase * DD + keyoff;

    const uint32_t kbH = sb + GK_OFF + (uint32_t)g * GRP_B;    // K hi (+KLO_D = lo)
    const uint32_t vb0 = kbH + 2 * KLO_D;                      // V buf0 / buf1
    const int barid = 1 + g;

    const uint32_t qa0 = sb + QH_OFF +
        (uint32_t)((gw * 16 + (lane & 7) + ((lane >> 3) & 1) * 8) * RSB + ((lane >> 4) & 1) * 16);
    const uint32_t krowoff =
        (uint32_t)(((lane & 7) + ((lane >> 4) & 1) * 8) * RSB + ((lane >> 3) & 1) * 16);
    const uint32_t vrowoff =
        (uint32_t)(((lane & 7) + ((lane >> 3) & 1) * 8) * RSB + ((lane >> 4) & 1) * 16);
    const int r0q = gw * 16 + (lane >> 2);    // thread rows: r0q, r0q+8

    // ---- prologue: Q (all threads) + pre-pass K0 hi; wait all, sync ----
    #pragma unroll
    for (int i = 0; i < 4; i++) {
        int idx = t + NTH * i;                // 0..2047
        int r = idx >> 4, c = idx & 15;
        uint32_t off = (uint32_t)(r * RSB + c * 16);
        cpa16(sb + QH_OFF + off, qh + (size_t)r * DD + c * 8);
        cpa16(sb + QH_OFF + QLO_D + off, ql + (size_t)r * DD + c * 8);
    }
    stage64h(tg, vb0, kh);                    // pre-pass K0 hi into V buf0
    CPA_COMMIT();
    CPA_WAIT0();
    __syncthreads();

    // ================= pre-pass: M~ = rowmax(Qhi Khi^T) ====================
    float mm0 = -3.402823466e38f, mm1 = -3.402823466e38f;
    #pragma unroll 1
    for (int i = 0; i < NCHG; i++) {
        if (i + 1 < NCHG)
            stage64h(tg, vb0 + (uint32_t)((i + 1) & 1) * KLO_D,
                     kh + (size_t)(i + 1) * 64 * DD);
        CPA_COMMIT();
        CPA_WAIT1();
        GBAR(barid);
        const uint32_t kb = vb0 + (uint32_t)(i & 1) * KLO_D;
        float S[8][4];
        #pragma unroll
        for (int r = 0; r < 8; r++) { S[r][0] = 0.f; S[r][1] = 0.f; S[r][2] = 0.f; S[r][3] = 0.f; }
        #pragma unroll
        for (int kt = 0; kt < 8; kt++) {
            uint32_t qh0, qh1, qh2, qh3;
            ldsm4(qh0, qh1, qh2, qh3, qa0 + kt * 32);
            #pragma unroll
            for (int ng = 0; ng < 4; ng++) {
                uint32_t ka = kb + (uint32_t)(ng * 16 * RSB) + krowoff + kt * 32;
                uint32_t k0, k1, k2, k3;
                ldsm4(k0, k1, k2, k3, ka);
                mma16816(S[2 * ng], qh0, qh1, qh2, qh3, k0, k1);
                mma16816(S[2 * ng + 1], qh0, qh1, qh2, qh3, k2, k3);
            }
        }
        #pragma unroll
        for (int nt = 0; nt < 8; nt++) {
            mm0 = fmaxf(mm0, fmaxf(S[nt][0], S[nt][1]));
            mm1 = fmaxf(mm1, fmaxf(S[nt][2], S[nt][3]));
        }
        GBAR(barid);
    }
    mm0 = fmaxf(mm0, __shfl_xor_sync(0xffffffffu, mm0, 1));
    mm0 = fmaxf(mm0, __shfl_xor_sync(0xffffffffu, mm0, 2));
    mm1 = fmaxf(mm1, __shfl_xor_sync(0xffffffffu, mm1, 1));
    mm1 = fmaxf(mm1, __shfl_xor_sync(0xffffffffu, mm1, 2));
    float* mtsm = (float*)(sm + MT_OFF);
    if ((lane & 3) == 0) {
        mtsm[g * 128 + r0q] = mm0;
        mtsm[g * 128 + r0q + 8] = mm1;
    }
    __syncthreads();
    const float Ms0 = fmaxf(mtsm[r0q], mtsm[128 + r0q]) + 0.25f;
    const float Ms1 = fmaxf(mtsm[r0q + 8], mtsm[128 + r0q + 8]) + 0.25f;
    __syncthreads();

    // ---- main prologue: K0 hi+lo + V0 hi, then V1 hi ----
    stage64g(tg, kbH, kh, kl);
    stage64h(tg, vb0, vh);
    CPA_COMMIT();
    stage64h(tg, vb0 + KLO_D, vh + (size_t)64 * DD);
    CPA_COMMIT();

    float O[16][4];
    #pragma unroll
    for (int n = 0; n < 16; n++) { O[n][0] = 0.f; O[n][1] = 0.f; O[n][2] = 0.f; O[n][3] = 0.f; }
    float l0 = 0.f, l1 = 0.f;

    float* wrow0 = out + OUT_W_OFF + (rowbase + q0 + r0q) * SS + g * 1024 + 2 * (lane & 3);
    float* wrow1 = wrow0 + (size_t)8 * SS;

    // =================== main loop: fixed-shift softmax ====================
    #pragma unroll 1
    for (int j = 0; j < NCHG; j++) {
        CPA_WAIT1();                           // K(j), V(j) landed; V(j+1) may pend
        GBAR(barid);

        // S(j): 16 rows x 64 keys, 3-term
        float S[8][4];
        #pragma unroll
        for (int r = 0; r < 8; r++) { S[r][0] = 0.f; S[r][1] = 0.f; S[r][2] = 0.f; S[r][3] = 0.f; }
        #pragma unroll
        for (int kt = 0; kt < 8; kt++) {
            uint32_t qh0, qh1, qh2, qh3, ql0, ql1, ql2, ql3;
            ldsm4(qh0, qh1, qh2, qh3, qa0 + kt * 32);
            ldsm4(ql0, ql1, ql2, ql3, qa0 + kt * 32 + QLO_D);
            #pragma unroll
            for (int ng = 0; ng < 4; ng++) {
                uint32_t ka = kbH + (uint32_t)(ng * 16 * RSB) + krowoff + kt * 32;
                uint32_t k0, k1, k2, k3, m0_, m1_, m2_, m3_;
                ldsm4(k0, k1, k2, k3, ka);
                ldsm4(m0_, m1_, m2_, m3_, ka + KLO_D);
                mma16816(S[2 * ng], qh0, qh1, qh2, qh3, k0, k1);
                mma16816(S[2 * ng], ql0, ql1, ql2, ql3, k0, k1);
                mma16816(S[2 * ng], qh0, qh1, qh2, qh3, m0_, m1_);
                mma16816(S[2 * ng + 1], qh0, qh1, qh2, qh3, k2, k3);
                mma16816(S[2 * ng + 1], ql0, ql1, ql2, ql3, k2, k3);
                mma16816(S[2 * ng + 1], qh0, qh1, qh2, qh3, m2_, m3_);
            }
        }
        GBAR(barid);                           // K(j) consumed
        if (j + 1 < NCHG)
            stage64g(tg, kbH, kh + (size_t)(j + 1) * 64 * DD,
                     kl + (size_t)(j + 1) * 64 * DD);
        CPA_COMMIT();

        // U = e^{s - M*}; accumulate l; write U (final up to x winv)
        #pragma unroll
        for (int nt = 0; nt < 8; nt++) {
            S[nt][0] = __expf(S[nt][0] - Ms0);
            S[nt][1] = __expf(S[nt][1] - Ms0);
            S[nt][2] = __expf(S[nt][2] - Ms1);
            S[nt][3] = __expf(S[nt][3] - Ms1);
            l0 += S[nt][0] + S[nt][1];
            l1 += S[nt][2] + S[nt][3];
        }
        #pragma unroll
        for (int nt = 0; nt < 8; nt++) {
            *(float2*)(wrow0 + j * 64 + nt * 8) = make_float2(S[nt][0], S[nt][1]);
            *(float2*)(wrow1 + j * 64 + nt * 8) = make_float2(S[nt][2], S[nt][3]);
        }

        // O += P V (2-term: PhVh + PlVh), V hi only
        const uint32_t vbH = vb0 + (uint32_t)(j & 1) * KLO_D;
        #pragma unroll
        for (int kt = 0; kt < 4; kt++) {
            uint32_t ph0, ph1, ph2, ph3, pl0, pl1, pl2, pl3;
            split2(S[2 * kt][0], S[2 * kt][1], ph0, pl0);
            split2(S[2 * kt][2], S[2 * kt][3], ph1, pl1);
            split2(S[2 * kt + 1][0], S[2 * kt + 1][1], ph2, pl2);
            split2(S[2 * kt + 1][2], S[2 * kt + 1][3], ph3, pl3);
            #pragma unroll
            for (int ng = 0; ng < 8; ng++) {
                uint32_t va = vbH + (uint32_t)(kt * 16 * RSB) + vrowoff + ng * 32;
                uint32_t x0, x1, x2, x3;
                ldsm4t(x0, x1, x2, x3, va);
                mma16816(O[2 * ng], ph0, ph1, ph2, ph3, x0, x1);
                mma16816(O[2 * ng], pl0, pl1, pl2, pl3, x0, x1);
                mma16816(O[2 * ng + 1], ph0, ph1, ph2, ph3, x2, x3);
                mma16816(O[2 * ng + 1], pl0, pl1, pl2, pl3, x2, x3);
            }
        }
        GBAR(barid);                           // V(j) consumed
        if (j + 2 < NCHG)
            stage64h(tg, vb0 + (uint32_t)(j & 1) * KLO_D,
                     vh + (size_t)(j + 2) * 64 * DD);
        CPA_COMMIT();
    }

    // =========================== epilogue ==================================
    l0 += __shfl_xor_sync(0xffffffffu, l0, 1);
    l0 += __shfl_xor_sync(0xffffffffu, l0, 2);
    l1 += __shfl_xor_sync(0xffffffffu, l1, 1);
    l1 += __shfl_xor_sync(0xffffffffu, l1, 2);
    float* lsm = (float*)(sm + LS_OFF);
    float* wvs = (float*)(sm + WV_OFF);
    if ((lane & 3) == 0) {
        lsm[g * 128 + r0q] = l0;
        lsm[g * 128 + r0q + 8] = l1;
    }
    __syncthreads();                           // both groups' loops complete
    const float linv0 = 1.0f / (lsm[r0q] + lsm[128 + r0q]);
    const float linv1 = 1.0f / (lsm[r0q + 8] + lsm[128 + r0q + 8]);
    if (g == 0 && (lane & 3) == 0) {
        wvs[r0q] = linv0;
        wvs[r0q + 8] = linv1;
    }

    float* ob = (float*)(sm + OMRG);           // [128][128]
    if (g == 1) {
        #pragma unroll
        for (int nt = 0; nt < 16; nt++) {
            int col = nt * 8 + (lane & 3) * 2;
            *(float2*)(ob + r0q * 128 + col) = make_float2(O[nt][0], O[nt][1]);
            *(float2*)(ob + (r0q + 8) * 128 + col) = make_float2(O[nt][2], O[nt][3]);
        }
    }
    __syncthreads();
    if (g == 0) {
        float* orow0 = out + (rowbase + q0 + r0q) * DD + 2 * (lane & 3);
        float* orow1 = orow0 + (size_t)8 * DD;
        #pragma unroll
        for (int nt = 0; nt < 16; nt++) {
            int col = nt * 8 + (lane & 3) * 2;
            float2 p0 = *(float2*)(ob + r0q * 128 + col);
            float2 p1 = *(float2*)(ob + (r0q + 8) * 128 + col);
            *(float2*)(orow0 + nt * 8) =
                make_float2((O[nt][0] + p0.x) * linv0, (O[nt][1] + p0.y) * linv0);
            *(float2*)(orow1 + nt * 8) =
                make_float2((O[nt][2] + p1.x) * linv1, (O[nt][3] + p1.y) * linv1);
        }
    }
    __syncthreads();

    // ============= W fixup: pure multiply (no exp) =========================
    float4* wbase = (float4*)(out + OUT_W_OFF + (rowbase + q0) * SS);
    #pragma unroll 4
    for (int i = 0; i < 128; i++) {
        int fi = t + NTH * i;                  // 0..65535
        float wv = wvs[fi >> 9];
        float4 v = wbase[fi];
        v.x *= wv; v.y *= wv; v.z *= wv; v.w *= wv;
        wbase[fi] = v;
    }
}

// ===========================================================================
extern "C" void kernel_launch(void* const* d_in, const int* in_sizes, int n_in,
                              void* d_out, int out_size) {
    const float* Q = (const float*)d_in[0];
    const float* K = (const float*)d_in[1];
    const float* V = (const float*)d_in[2];
    float* out = (float*)d_out;

    cudaFuncSetAttribute(attn_mma, cudaFuncAttributeMaxDynamicSharedMemorySize, SMEM_TOTAL);

    prep_split<<<dim3((BB * SS * DD) / 256, 3), 256>>>(Q, K, V);
    attn_mma<<<BB * (SS / 128), NTH, SMEM_TOTAL>>>(out);
}